// round 5
// baseline (speedup 1.0000x reference)
#include <cuda_runtime.h>
#include <cstdint>

// ---------------------------------------------------------------------------
// Boltzmann collision operator, spectral method. N=48, B=8, M=5 -> 20 modes.
// Round 5: chunked producer/consumer scheduling so the big intermediate
//          (formerly 297MB) lives in a reused 42.5MB L2-resident scratch;
//          stage-A-from-global register FFTs (fused weight multiply),
//          cross-buffer stage-B, register twiddles, RMW accumulators.
// ---------------------------------------------------------------------------

#define NN    48
#define N2P   (NN*NN)        // 2304
#define N3    (NN*NN*NN)     // 110592
#define NB    8
#define NCH   3              // pairs per chunk
#define NCHUNK 7             // 21 / NCH
#define LDP   49             // padded smem row (float2 units)
#define NTHR  384
#define PI_F  3.14159265358979323846f

// scratch (__device__ globals; no runtime allocation)
__device__ float2 g_spec[NB * N3];                         // ~7 MB   (L2-ish)
__device__ float2 g_SC[(size_t)NCH * NB * 2 * N3];         // ~42.5MB reused scratch
__device__ float  g_acc[(size_t)NCH * NB * N3];            // ~10.6MB accumulators

__device__ __forceinline__ float2 cadd(float2 a, float2 b){ return make_float2(a.x+b.x, a.y+b.y); }
__device__ __forceinline__ float2 csub(float2 a, float2 b){ return make_float2(a.x-b.x, a.y-b.y); }
__device__ __forceinline__ float2 cmul(float2 a, float2 b){
    return make_float2(a.x*b.x - a.y*b.y, a.x*b.y + a.y*b.x);
}

__device__ __forceinline__ void dft3(float2 a, float2 b, float2 c,
                                     float2& X0, float2& X1, float2& X2){
    float2 t1 = cadd(b, c);
    X0 = cadd(a, t1);
    float2 m = make_float2(a.x - 0.5f*t1.x, a.y - 0.5f*t1.y);
    const float K = 0.8660254037844386f;
    float2 s = make_float2(K*(b.x - c.x), K*(b.y - c.y));
    X1 = make_float2(m.x + s.y, m.y - s.x);   // m - i*s
    X2 = make_float2(m.x - s.y, m.y + s.x);   // m + i*s
}

// per-thread register twiddles: twr[k1] = e^{-2pi i * n2 * k1 / 48}, n2 = tid&7
__device__ __forceinline__ void make_tw(float2 twr[6]){
    int n2 = threadIdx.x & 7;
    twr[0] = make_float2(1.0f, 0.0f);
    #pragma unroll
    for (int k1 = 1; k1 < 6; k1++){
        float sv, cv;
        sincosf(-2.0f*PI_F * (float)(n2*k1) / 48.0f, &sv, &cv);
        twr[k1] = make_float2(cv, sv);
    }
}

// DFT6 + twiddle, registers in -> registers out
__device__ __forceinline__ void dft6_tw(const float2 x[6], const float2 twr[6], float2 y[6]){
    float2 E0,E1,E2, O0,O1,O2;
    dft3(x[0], x[2], x[4], E0, E1, E2);
    dft3(x[1], x[3], x[5], O0, O1, O2);
    const float K = 0.8660254037844386f;
    float2 o1 = cmul(O1, make_float2( 0.5f, -K));
    float2 o2 = cmul(O2, make_float2(-0.5f, -K));
    y[0] = cadd(E0, O0);
    y[1] = cmul(cadd(E1, o1), twr[1]);
    y[2] = cmul(cadd(E2, o2), twr[2]);
    y[3] = cmul(csub(E0, O0), twr[3]);
    y[4] = cmul(csub(E1, o1), twr[4]);
    y[5] = cmul(csub(E2, o2), twr[5]);
}

__device__ __forceinline__ void dft8(const float2* r, float2* o){
    float2 t0 = cadd(r[0],r[4]), t1 = csub(r[0],r[4]);
    float2 t2 = cadd(r[2],r[6]), t3 = csub(r[2],r[6]);
    float2 E0 = cadd(t0,t2), E2 = csub(t0,t2);
    float2 E1 = make_float2(t1.x + t3.y, t1.y - t3.x);
    float2 E3 = make_float2(t1.x - t3.y, t1.y + t3.x);
    float2 u0 = cadd(r[1],r[5]), u1 = csub(r[1],r[5]);
    float2 u2 = cadd(r[3],r[7]), u3 = csub(r[3],r[7]);
    float2 Q0 = cadd(u0,u2), Q2 = csub(u0,u2);
    float2 Q1 = make_float2(u1.x + u3.y, u1.y - u3.x);
    float2 Q3 = make_float2(u1.x - u3.y, u1.y + u3.x);
    const float S2 = 0.7071067811865476f;
    float2 p1 = cmul(Q1, make_float2( S2, -S2));
    float2 p2 = make_float2(Q2.y, -Q2.x);
    float2 p3 = cmul(Q3, make_float2(-S2, -S2));
    o[0] = cadd(E0,Q0); o[1] = cadd(E1,p1); o[2] = cadd(E2,p2); o[3] = cadd(E3,p3);
    o[4] = csub(E0,Q0); o[5] = csub(E1,p1); o[6] = csub(E2,p2); o[7] = csub(E3,p3);
}

// store stage-A outputs: slot (n2 + 8*k1) of the thread's line
template <int LDR, int LDL>
__device__ __forceinline__ void stA_store(float2* s, int line, int n2, const float2 y[6]){
    float2* base = s + line*LDL + n2*LDR;
    #pragma unroll
    for (int k1 = 0; k1 < 6; k1++) base[(8*k1)*LDR] = y[k1];
}

// stage A in-place from smem (thread-private slots, no internal sync needed)
template <int LDR, int LDL>
__device__ __forceinline__ void stageA_ip(float2* s, const float2 twr[6]){
    const int w = threadIdx.x;
    int line = w >> 3, n2 = w & 7;
    float2* base = s + line*LDL + n2*LDR;
    float2 x[6], y[6];
    #pragma unroll
    for (int i = 0; i < 6; i++) x[i] = base[(8*i)*LDR];
    dft6_tw(x, twr, y);
    #pragma unroll
    for (int k1 = 0; k1 < 6; k1++) base[(8*k1)*LDR] = y[k1];
}

// stage B cross-buffer: src -> dst (different buffers, no mid sync)
template <int LDR, int LDL>
__device__ __forceinline__ void stageB_x(const float2* src, float2* dst){
    const int w = threadIdx.x;
    if (w >= 288) return;
    int line = w % 48, k1 = w / 48;
    const float2* b = src + line*LDL + (k1*8)*LDR;
    float2 r[8], o[8];
    #pragma unroll
    for (int i = 0; i < 8; i++) r[i] = b[i*LDR];
    dft8(r, o);
    float2* d = dst + line*LDL + k1*LDR;
    #pragma unroll
    for (int i = 0; i < 8; i++) d[(6*i)*LDR] = o[i];
}

// K1: f * (-1)^(x+y+z); FFT z then y. CTA = (b, x-plane).
__global__ void __launch_bounds__(NTHR) k_fwd1(const float* __restrict__ f){
    __shared__ float2 s1[48*LDP];
    __shared__ float2 s2[48*LDP];
    float2 twr[6]; make_tw(twr);
    int b = blockIdx.x / 48, x = blockIdx.x % 48;
    const int w = threadIdx.x;
    // zA: global -> s1 (line = y, element = z = n2+8i)
    {
        int yl = w >> 3, n2 = w & 7;
        const float* src = f + (size_t)b*N3 + x*N2P + yl*48 + n2;
        float sg = ((x + yl + n2) & 1) ? -1.0f : 1.0f;
        float2 xa[6], ya[6];
        #pragma unroll
        for (int i = 0; i < 6; i++) xa[i] = make_float2(sg * src[8*i], 0.0f);
        dft6_tw(xa, twr, ya);
        stA_store<1, LDP>(s1, yl, n2, ya);
    }
    __syncthreads();
    stageB_x<1, LDP>(s1, s2);          // zB: s1 -> s2
    __syncthreads();
    stageA_ip<LDP, 1>(s2, twr);        // yA in place (element = y stride LDP)
    __syncthreads();
    // yB: s2 -> global
    if (w < 288){
        int line = w % 48, k1 = w / 48;     // line = z
        const float2* bb = s2 + line + (k1*8)*LDP;
        float2 r[8], o[8];
        #pragma unroll
        for (int i = 0; i < 8; i++) r[i] = bb[i*LDP];
        dft8(r, o);
        float2* dst = g_spec + (size_t)b*N3 + x*N2P;
        #pragma unroll
        for (int i = 0; i < 8; i++) dst[(k1+6*i)*48 + line] = o[i];
    }
}

// K2: FFT x, scale 1/N^3, in place in g_spec. CTA = (b, y-plane). One barrier.
__global__ void __launch_bounds__(NTHR) k_fwd2(){
    __shared__ float2 s1[48*LDP];
    float2 twr[6]; make_tw(twr);
    int b = blockIdx.x / 48, y = blockIdx.x % 48;
    const int w = threadIdx.x;
    float2* base = g_spec + (size_t)b*N3 + y*48;
    // xA: global -> s1 (line = z, element = x)
    {
        int zl = w >> 3, n2 = w & 7;
        float2 xa[6], ya[6];
        #pragma unroll
        for (int i = 0; i < 6; i++) xa[i] = base[(size_t)(n2+8*i)*N2P + zl];
        dft6_tw(xa, twr, ya);
        stA_store<LDP, 1>(s1, zl, n2, ya);
    }
    __syncthreads();
    // xB: s1 -> global, scaled
    if (w < 288){
        int line = w % 48, k1 = w / 48;     // line = z
        const float2* bb = s1 + line + (k1*8)*LDP;
        float2 r[8], o[8];
        #pragma unroll
        for (int i = 0; i < 8; i++) r[i] = bb[i*LDP];
        dft8(r, o);
        const float inv = 1.0f / (float)N3;
        #pragma unroll
        for (int i = 0; i < 8; i++)
            base[(size_t)(k1+6*i)*N2P + line] = make_float2(o[i].x*inv, o[i].y*inv);
    }
}

// K3 (per chunk): uG = fs*wG, uH = fs*wH; FFT z then y -> scratch.
// CTA = (pp, b, x-plane). Dynamic smem: 4 plane buffers (ping-pong).
__global__ void __launch_bounds__(NTHR) k_mulfft(const float* __restrict__ phi,
                                                 const float* __restrict__ psi,
                                                 const float* __restrict__ phipsi,
                                                 int nb, int p0){
    extern __shared__ float2 sm[];
    float2* s1G = sm;
    float2* s1H = sm + 48*LDP;
    float2* s2G = sm + 2*48*LDP;
    float2* s2H = sm + 3*48*LDP;
    float2 twr[6]; make_tw(twr);
    int x  = blockIdx.x % 48;
    int bv = blockIdx.x / 48;
    int b  = bv % nb;
    int pp = bv / nb;
    int p  = p0 + pp;
    const int w = threadIdx.x;
    const float2* fs = g_spec + (size_t)b*N3 + x*N2P;
    const float* wG = (p < 20) ? (phi + (size_t)p*N3 + x*N2P) : (phipsi + (size_t)x*N2P);
    const float* wH = (p < 20) ? (psi + (size_t)p*N3 + x*N2P) : nullptr;

    // zA: global (fs * w) -> s1G/s1H  (line = y, element = z)
    {
        int yl = w >> 3, n2 = w & 7;
        const float2* fr = fs + yl*48 + n2;
        const float*  gr = wG + yl*48 + n2;
        float2 xg[6], xh[6], yg[6], yh[6];
        #pragma unroll
        for (int i = 0; i < 6; i++){
            float2 v = fr[8*i];
            float gw = gr[8*i];
            float hw = wH ? wH[yl*48 + n2 + 8*i] : 1.0f;
            xg[i] = make_float2(v.x*gw, v.y*gw);
            xh[i] = make_float2(v.x*hw, v.y*hw);
        }
        dft6_tw(xg, twr, yg);
        dft6_tw(xh, twr, yh);
        stA_store<1, LDP>(s1G, yl, n2, yg);
        stA_store<1, LDP>(s1H, yl, n2, yh);
    }
    __syncthreads();
    stageB_x<1, LDP>(s1G, s2G);        // zB cross-buffer
    stageB_x<1, LDP>(s1H, s2H);
    __syncthreads();
    stageA_ip<LDP, 1>(s2G, twr);       // yA in place
    stageA_ip<LDP, 1>(s2H, twr);
    __syncthreads();
    // yB: s2 -> scratch
    if (w < 288){
        int line = w % 48, k1 = w / 48;     // line = z
        float2 ra[8], rb[8], oa[8], ob[8];
        const float2* ba = s2G + line + (k1*8)*LDP;
        const float2* bb = s2H + line + (k1*8)*LDP;
        #pragma unroll
        for (int i = 0; i < 8; i++){ ra[i] = ba[i*LDP]; rb[i] = bb[i*LDP]; }
        dft8(ra, oa);
        dft8(rb, ob);
        float2* dstG = g_SC + (size_t)((pp*NB + b)*2 + 0)*N3 + x*N2P;
        float2* dstH = g_SC + (size_t)((pp*NB + b)*2 + 1)*N3 + x*N2P;
        #pragma unroll
        for (int i = 0; i < 8; i++){
            dstG[(k1+6*i)*48 + line] = oa[i];
            dstH[(k1+6*i)*48 + line] = ob[i];
        }
    }
}

// K4 (per chunk): finish x-FFT of G,H in registers; accumulate signed Re(G*H)
// into per-pp accumulator slab via deterministic RMW. CTA = (pp, b, y-plane).
__global__ void __launch_bounds__(NTHR) k_pair(int nb, int p0, int first){
    __shared__ float2 s1G[48*LDP];
    __shared__ float2 s1H[48*LDP];
    float2 twr[6]; make_tw(twr);
    int y  = blockIdx.x % 48;
    int bv = blockIdx.x / 48;
    int b  = bv % nb;
    int pp = bv / nb;
    int p  = p0 + pp;
    float sgn = (p < 20) ? 1.0f : -1.0f;
    const int w = threadIdx.x;
    const float2* srcG = g_SC + (size_t)((pp*NB + b)*2 + 0)*N3 + y*48;
    const float2* srcH = g_SC + (size_t)((pp*NB + b)*2 + 1)*N3 + y*48;

    // xA: global -> s1G/s1H (line = z, element = x)
    {
        int zl = w >> 3, n2 = w & 7;
        float2 xg[6], xh[6], yg[6], yh[6];
        #pragma unroll
        for (int i = 0; i < 6; i++){
            xg[i] = srcG[(size_t)(n2+8*i)*N2P + zl];
            xh[i] = srcH[(size_t)(n2+8*i)*N2P + zl];
        }
        dft6_tw(xg, twr, yg);
        dft6_tw(xh, twr, yh);
        stA_store<LDP, 1>(s1G, zl, n2, yg);
        stA_store<LDP, 1>(s1H, zl, n2, yh);
    }
    __syncthreads();
    // xB: smem -> registers -> product -> RMW accumulate
    if (w < 288){
        int line = w % 48, k1 = w / 48;     // line = z
        float2 ra[8], rb[8], oa[8], ob[8];
        const float2* ba = s1G + line + (k1*8)*LDP;
        const float2* bb = s1H + line + (k1*8)*LDP;
        #pragma unroll
        for (int i = 0; i < 8; i++){ ra[i] = ba[i*LDP]; rb[i] = bb[i*LDP]; }
        dft8(ra, oa);
        dft8(rb, ob);
        float* dst = g_acc + (size_t)(pp*NB + b)*N3 + y*48;
        if (first){
            #pragma unroll
            for (int i = 0; i < 8; i++)
                dst[(size_t)(k1+6*i)*N2P + line] = sgn * (oa[i].x*ob[i].x - oa[i].y*ob[i].y);
        } else {
            #pragma unroll
            for (int i = 0; i < 8; i++){
                size_t a = (size_t)(k1+6*i)*N2P + line;
                dst[a] += sgn * (oa[i].x*ob[i].x - oa[i].y*ob[i].y);
            }
        }
    }
}

// K5: Q = scale * (acc0 + acc1 + acc2), vectorized.
__global__ void __launch_bounds__(256) k_combine(float* __restrict__ Q,
                                                 const float* __restrict__ kn,
                                                 int nb){
    int idx = blockIdx.x * 256 + threadIdx.x;
    int total4 = nb * N3 / 4;
    if (idx >= total4) return;
    size_t stride4 = (size_t)NB * N3 / 4;   // slab stride in float4 (alloc uses NB)
    const float4* src = (const float4*)g_acc;
    // account for nb<NB layout: slabs are at pp*NB*N3, batches packed 0..nb-1
    int bslot = idx / (N3/4);
    int inner = idx % (N3/4);
    size_t off = (size_t)bslot*(N3/4) + inner;
    float4 a = src[off];
    float4 c = src[stride4 + off];
    float4 d = src[2*stride4 + off];
    const float scale = 4.0f*PI_F*PI_F / (kn[0] * 25.0f);
    ((float4*)Q)[idx] = make_float4(scale*(a.x+c.x+d.x), scale*(a.y+c.y+d.y),
                                    scale*(a.z+c.z+d.z), scale*(a.w+c.w+d.w));
}

extern "C" void kernel_launch(void* const* d_in, const int* in_sizes, int n_in,
                              void* d_out, int out_size){
    const float* f      = (const float*)d_in[0];
    const float* kn     = (const float*)d_in[1];
    const float* phi    = (const float*)d_in[2];
    const float* psi    = (const float*)d_in[3];
    const float* phipsi = (const float*)d_in[4];
    float* Q = (float*)d_out;

    int nb = in_sizes[0] / N3;   // = 8
    if (nb > NB) nb = NB;

    const int SMEM_MF = 4 * 48 * LDP * (int)sizeof(float2);   // 75264 B
    cudaFuncSetAttribute(k_mulfft, cudaFuncAttributeMaxDynamicSharedMemorySize, SMEM_MF);

    k_fwd1<<<nb*48, NTHR>>>(f);
    k_fwd2<<<nb*48, NTHR>>>();
    for (int c = 0; c < NCHUNK; c++){
        k_mulfft<<<NCH*nb*48, NTHR, SMEM_MF>>>(phi, psi, phipsi, nb, 3*c);
        k_pair  <<<NCH*nb*48, NTHR>>>(nb, 3*c, c == 0 ? 1 : 0);
    }
    k_combine<<<(nb*N3/4 + 255)/256, 256>>>(Q, kn, nb);
}

// round 6
// speedup vs baseline: 1.0206x; 1.0206x over previous
#include <cuda_runtime.h>
#include <cstdint>

// ---------------------------------------------------------------------------
// Boltzmann collision operator, spectral method. N=48, B=8, M=5 -> 20 modes.
// Round 6 = Round 4 schedule (best known) + register twiddles everywhere +
//           fused coalesced zA-from-global in k_mulfft (one less smem pass,
//           one less barrier), 2-buffer static smem for full occupancy.
// ---------------------------------------------------------------------------

#define NN    48
#define N2P   (NN*NN)        // 2304
#define N3    (NN*NN*NN)     // 110592
#define NB    8
#define NJ    42             // 20 phi + 20 psi + phipsi + identity
#define NPG   3              // pairs per k_pair CTA
#define NGRP  7              // 21 / NPG partial slabs
#define LDP   49             // padded smem row (float2 units)
#define NTHR  384
#define PI_F  3.14159265358979323846f

// scratch (__device__ globals; no runtime allocation)
__device__ float2 g_spec[NB * N3];                    // ~7 MB
__device__ float2 g_S[(size_t)NB * NJ * N3];          // ~297 MB
__device__ float  g_part[(size_t)NGRP * NB * N3];     // ~25 MB signed partials

__device__ __forceinline__ float2 cadd(float2 a, float2 b){ return make_float2(a.x+b.x, a.y+b.y); }
__device__ __forceinline__ float2 csub(float2 a, float2 b){ return make_float2(a.x-b.x, a.y-b.y); }
__device__ __forceinline__ float2 cmul(float2 a, float2 b){
    return make_float2(a.x*b.x - a.y*b.y, a.x*b.y + a.y*b.x);
}

__device__ __forceinline__ void dft3(float2 a, float2 b, float2 c,
                                     float2& X0, float2& X1, float2& X2){
    float2 t1 = cadd(b, c);
    X0 = cadd(a, t1);
    float2 m = make_float2(a.x - 0.5f*t1.x, a.y - 0.5f*t1.y);
    const float K = 0.8660254037844386f;
    float2 s = make_float2(K*(b.x - c.x), K*(b.y - c.y));
    X1 = make_float2(m.x + s.y, m.y - s.x);   // m - i*s
    X2 = make_float2(m.x - s.y, m.y + s.x);   // m + i*s
}

// per-thread register twiddles: twr[k1] = e^{-2pi i * n2 * k1 / 48}, n2 = tid&7
__device__ __forceinline__ void make_tw(float2 twr[6]){
    int n2 = threadIdx.x & 7;
    twr[0] = make_float2(1.0f, 0.0f);
    #pragma unroll
    for (int k1 = 1; k1 < 6; k1++){
        float sv, cv;
        sincosf(-2.0f*PI_F * (float)(n2*k1) / 48.0f, &sv, &cv);
        twr[k1] = make_float2(cv, sv);
    }
}

// DFT6 + twiddle, registers in -> registers out
__device__ __forceinline__ void dft6_tw(const float2 x[6], const float2 twr[6], float2 y[6]){
    float2 E0,E1,E2, O0,O1,O2;
    dft3(x[0], x[2], x[4], E0, E1, E2);
    dft3(x[1], x[3], x[5], O0, O1, O2);
    const float K = 0.8660254037844386f;
    float2 o1 = cmul(O1, make_float2( 0.5f, -K));
    float2 o2 = cmul(O2, make_float2(-0.5f, -K));
    y[0] = cadd(E0, O0);
    y[1] = cmul(cadd(E1, o1), twr[1]);
    y[2] = cmul(cadd(E2, o2), twr[2]);
    y[3] = cmul(csub(E0, O0), twr[3]);
    y[4] = cmul(csub(E1, o1), twr[4]);
    y[5] = cmul(csub(E2, o2), twr[5]);
}

__device__ __forceinline__ void dft8(const float2* r, float2* o){
    float2 t0 = cadd(r[0],r[4]), t1 = csub(r[0],r[4]);
    float2 t2 = cadd(r[2],r[6]), t3 = csub(r[2],r[6]);
    float2 E0 = cadd(t0,t2), E2 = csub(t0,t2);
    float2 E1 = make_float2(t1.x + t3.y, t1.y - t3.x);
    float2 E3 = make_float2(t1.x - t3.y, t1.y + t3.x);
    float2 u0 = cadd(r[1],r[5]), u1 = csub(r[1],r[5]);
    float2 u2 = cadd(r[3],r[7]), u3 = csub(r[3],r[7]);
    float2 Q0 = cadd(u0,u2), Q2 = csub(u0,u2);
    float2 Q1 = make_float2(u1.x + u3.y, u1.y - u3.x);
    float2 Q3 = make_float2(u1.x - u3.y, u1.y + u3.x);
    const float S2 = 0.7071067811865476f;
    float2 p1 = cmul(Q1, make_float2( S2, -S2));
    float2 p2 = make_float2(Q2.y, -Q2.x);
    float2 p3 = cmul(Q3, make_float2(-S2, -S2));
    o[0] = cadd(E0,Q0); o[1] = cadd(E1,p1); o[2] = cadd(E2,p2); o[3] = cadd(E3,p3);
    o[4] = csub(E0,Q0); o[5] = csub(E1,p1); o[6] = csub(E2,p2); o[7] = csub(E3,p3);
}

// store stage-A outputs: slot (n2 + 8*k1) of the thread's line
template <int LDR, int LDL>
__device__ __forceinline__ void stA_store(float2* s, int line, int n2, const float2 y[6]){
    float2* base = s + line*LDL + n2*LDR;
    #pragma unroll
    for (int k1 = 0; k1 < 6; k1++) base[(8*k1)*LDR] = y[k1];
}

// stage A in-place from smem (thread-private slots, no internal sync needed)
template <int LDR, int LDL>
__device__ __forceinline__ void stageA_ip(float2* s, const float2 twr[6]){
    const int w = threadIdx.x;
    int line = w >> 3, n2 = w & 7;
    float2* base = s + line*LDL + n2*LDR;
    float2 x[6], y[6];
    #pragma unroll
    for (int i = 0; i < 6; i++) x[i] = base[(8*i)*LDR];
    dft6_tw(x, twr, y);
    #pragma unroll
    for (int k1 = 0; k1 < 6; k1++) base[(8*k1)*LDR] = y[k1];
}

// dual-plane stage B, in place, read-sync-write (shared barrier for both planes)
template <int LDR, int LDL>
__device__ __forceinline__ void stageB2_ip(float2* sA, float2* sB){
    const int w = threadIdx.x;
    int line = w % 48, k1 = w / 48;
    bool act = (w < 288);
    float2 ra[8], rb[8];
    if (act){
        const float2* ba = sA + line*LDL + (k1*8)*LDR;
        const float2* bb = sB + line*LDL + (k1*8)*LDR;
        #pragma unroll
        for (int i = 0; i < 8; i++){ ra[i] = ba[i*LDR]; rb[i] = bb[i*LDR]; }
    }
    __syncthreads();
    if (act){
        float2 oa[8], ob[8];
        dft8(ra, oa);
        dft8(rb, ob);
        float2* da = sA + line*LDL + k1*LDR;
        float2* db = sB + line*LDL + k1*LDR;
        #pragma unroll
        for (int i = 0; i < 8; i++){ da[(6*i)*LDR] = oa[i]; db[(6*i)*LDR] = ob[i]; }
    }
}

// K1: f * (-1)^(x+y+z); FFT z then y. CTA = (b, x-plane).
__global__ void __launch_bounds__(NTHR) k_fwd1(const float* __restrict__ f){
    __shared__ float2 s1[48*LDP];
    __shared__ float2 s2[48*LDP];
    float2 twr[6]; make_tw(twr);
    int b = blockIdx.x / 48, x = blockIdx.x % 48;
    const int w = threadIdx.x;
    // zA: global -> s1 (line = y, element = z = n2+8i)
    {
        int yl = w >> 3, n2 = w & 7;
        const float* src = f + (size_t)b*N3 + x*N2P + yl*48 + n2;
        float sg = ((x + yl + n2) & 1) ? -1.0f : 1.0f;
        float2 xa[6], ya[6];
        #pragma unroll
        for (int i = 0; i < 6; i++) xa[i] = make_float2(sg * src[8*i], 0.0f);
        dft6_tw(xa, twr, ya);
        stA_store<1, LDP>(s1, yl, n2, ya);
    }
    __syncthreads();
    // zB: s1 -> s2 (cross-buffer, no mid sync)
    if (w < 288){
        int line = w % 48, k1 = w / 48;
        const float2* bb = s1 + line*LDP + k1*8;
        float2 r[8], o[8];
        #pragma unroll
        for (int i = 0; i < 8; i++) r[i] = bb[i];
        dft8(r, o);
        float2* d = s2 + line*LDP + k1;
        #pragma unroll
        for (int i = 0; i < 8; i++) d[6*i] = o[i];
    }
    __syncthreads();
    stageA_ip<LDP, 1>(s2, twr);        // yA in place (element = y stride LDP)
    __syncthreads();
    // yB: s2 -> global
    if (w < 288){
        int line = w % 48, k1 = w / 48;     // line = z
        const float2* bb = s2 + line + (k1*8)*LDP;
        float2 r[8], o[8];
        #pragma unroll
        for (int i = 0; i < 8; i++) r[i] = bb[i*LDP];
        dft8(r, o);
        float2* dst = g_spec + (size_t)b*N3 + x*N2P;
        #pragma unroll
        for (int i = 0; i < 8; i++) dst[(k1+6*i)*48 + line] = o[i];
    }
}

// K2: FFT x, scale 1/N^3, in place in g_spec. CTA = (b, y-plane). One barrier.
__global__ void __launch_bounds__(NTHR) k_fwd2(){
    __shared__ float2 s1[48*LDP];
    float2 twr[6]; make_tw(twr);
    int b = blockIdx.x / 48, y = blockIdx.x % 48;
    const int w = threadIdx.x;
    float2* base = g_spec + (size_t)b*N3 + y*48;
    // xA: global -> s1 (line = z, element = x)
    {
        int zl = w >> 3, n2 = w & 7;
        float2 xa[6], ya[6];
        #pragma unroll
        for (int i = 0; i < 6; i++) xa[i] = base[(size_t)(n2+8*i)*N2P + zl];
        dft6_tw(xa, twr, ya);
        stA_store<LDP, 1>(s1, zl, n2, ya);
    }
    __syncthreads();
    // xB: s1 -> global, scaled
    if (w < 288){
        int line = w % 48, k1 = w / 48;     // line = z
        const float2* bb = s1 + line + (k1*8)*LDP;
        float2 r[8], o[8];
        #pragma unroll
        for (int i = 0; i < 8; i++) r[i] = bb[i*LDP];
        dft8(r, o);
        const float inv = 1.0f / (float)N3;
        #pragma unroll
        for (int i = 0; i < 8; i++)
            base[(size_t)(k1+6*i)*N2P + line] = make_float2(o[i].x*inv, o[i].y*inv);
    }
}

// K3: dual-plane uG = fs*wG, uH = fs*wH; FFT z then y -> g_S.
//     zA fused with the (coalesced) global load; zB in place; yA in place;
//     yB stage-B registers -> global. 3 barriers + 1 inside stageB2_ip.
//     Batch fastest in blockIdx for weight L2 reuse.
__global__ void __launch_bounds__(NTHR) k_mulfft(const float* __restrict__ phi,
                                                 const float* __restrict__ psi,
                                                 const float* __restrict__ phipsi,
                                                 int nb){
    __shared__ float2 sG[48*LDP];
    __shared__ float2 sH[48*LDP];
    float2 twr[6]; make_tw(twr);
    int x  = blockIdx.x % 48;
    int bv = blockIdx.x / 48;
    int b  = bv % nb;
    int p  = bv / nb;            // 0..20
    int jG = (p < 20) ? p      : 40;
    int jH = (p < 20) ? 20 + p : 41;
    const int w = threadIdx.x;
    const float2* fs = g_spec + (size_t)b*N3 + x*N2P;
    const float* wG = (p < 20) ? (phi + (size_t)p*N3 + x*N2P) : (phipsi + (size_t)x*N2P);
    const float* wH = (p < 20) ? (psi + (size_t)p*N3 + x*N2P) : nullptr;

    // zA: global (fs*w) -> smem (line = y, element = z = n2+8i)
    {
        int yl = w >> 3, n2 = w & 7;
        int off = yl*48 + n2;
        float2 xg[6], xh[6], yg[6], yh[6];
        #pragma unroll
        for (int i = 0; i < 6; i++){
            float2 v = fs[off + 8*i];
            float gw = wG[off + 8*i];
            float hw = wH ? wH[off + 8*i] : 1.0f;
            xg[i] = make_float2(v.x*gw, v.y*gw);
            xh[i] = make_float2(v.x*hw, v.y*hw);
        }
        dft6_tw(xg, twr, yg);
        dft6_tw(xh, twr, yh);
        stA_store<1, LDP>(sG, yl, n2, yg);
        stA_store<1, LDP>(sH, yl, n2, yh);
    }
    __syncthreads();
    stageB2_ip<1, LDP>(sG, sH);        // zB in place (internal sync)
    __syncthreads();
    stageA_ip<LDP, 1>(sG, twr);        // yA in place
    stageA_ip<LDP, 1>(sH, twr);
    __syncthreads();
    // yB: smem -> global
    if (w < 288){
        int line = w % 48, k1 = w / 48;     // line = z
        float2 ra[8], rb[8], oa[8], ob[8];
        const float2* ba = sG + line + (k1*8)*LDP;
        const float2* bb = sH + line + (k1*8)*LDP;
        #pragma unroll
        for (int i = 0; i < 8; i++){ ra[i] = ba[i*LDP]; rb[i] = bb[i*LDP]; }
        dft8(ra, oa);
        dft8(rb, ob);
        float2* dstG = g_S + (size_t)(b*NJ + jG)*N3 + x*N2P;
        float2* dstH = g_S + (size_t)(b*NJ + jH)*N3 + x*N2P;
        #pragma unroll
        for (int i = 0; i < 8; i++){
            dstG[(k1+6*i)*48 + line] = oa[i];
            dstH[(k1+6*i)*48 + line] = ob[i];
        }
    }
}

// K4: one (group g of NPG pairs, batch b, y-plane) per CTA.
//     Per pair: coalesced float4 staging, x-FFT stage A in smem, stage B in
//     registers, signed product accumulated across pairs, single store.
__global__ void __launch_bounds__(NTHR) k_pair(int nb){
    __shared__ float2 sG[48*LDP];
    __shared__ float2 sH[48*LDP];
    float2 twr[6]; make_tw(twr);
    int y  = blockIdx.x % 48;
    int bv = blockIdx.x / 48;
    int b  = bv % nb;
    int g  = bv / nb;            // 0..6
    const int w = threadIdx.x;
    const int line = w % 48, k1 = w / 48;
    const bool act = (w < 288);
    float acc[8];
    #pragma unroll
    for (int i = 0; i < 8; i++) acc[i] = 0.0f;

    for (int pp = 0; pp < NPG; pp++){
        int p  = g*NPG + pp;
        int jG = (p < 20) ? p      : 40;
        int jH = (p < 20) ? 20 + p : 41;
        float sgn = (p < 20) ? 1.0f : -1.0f;
        const float2* srcG = g_S + (size_t)(b*NJ + jG)*N3 + y*48;
        const float2* srcH = g_S + (size_t)(b*NJ + jH)*N3 + y*48;
        for (int i = threadIdx.x; i < N2P/2; i += NTHR){
            int x = i/24, q = i%24;
            int z0 = q*2;
            float4 gv = *(const float4*)(srcG + x*N2P + z0);
            float4 hv = *(const float4*)(srcH + x*N2P + z0);
            sG[x*LDP + z0    ] = make_float2(gv.x, gv.y);
            sG[x*LDP + z0 + 1] = make_float2(gv.z, gv.w);
            sH[x*LDP + z0    ] = make_float2(hv.x, hv.y);
            sH[x*LDP + z0 + 1] = make_float2(hv.z, hv.w);
        }
        __syncthreads();
        // x-lines: element stride LDP, line (=z) stride 1
        stageA_ip<LDP, 1>(sG, twr);
        stageA_ip<LDP, 1>(sH, twr);
        __syncthreads();
        if (act){
            float2 ra[8], rb[8], oa[8], ob[8];
            const float2* ba = sG + line + (k1*8)*LDP;
            const float2* bb = sH + line + (k1*8)*LDP;
            #pragma unroll
            for (int i = 0; i < 8; i++){ ra[i] = ba[i*LDP]; rb[i] = bb[i*LDP]; }
            dft8(ra, oa);
            dft8(rb, ob);
            #pragma unroll
            for (int i = 0; i < 8; i++)
                acc[i] += sgn * (oa[i].x*ob[i].x - oa[i].y*ob[i].y);
        }
        __syncthreads();   // protect sG/sH before next pair's loads
    }

    if (act){
        float* dst = g_part + (size_t)(g*nb + b)*N3 + y*48;
        #pragma unroll
        for (int i = 0; i < 8; i++){
            int x = k1 + 6*i;
            dst[(size_t)x*N2P + line] = acc[i];
        }
    }
}

// K5: deterministic combine: Q = scale * sum_g partial_g (float4).
__global__ void __launch_bounds__(256) k_combine(float* __restrict__ Q,
                                                 const float* __restrict__ kn,
                                                 int nb){
    int idx = blockIdx.x * 256 + threadIdx.x;
    int total4 = nb * N3 / 4;
    if (idx >= total4) return;
    const float4* src = (const float4*)g_part + idx;
    size_t stride4 = (size_t)nb * N3 / 4;
    float4 a = make_float4(0.f, 0.f, 0.f, 0.f);
    #pragma unroll
    for (int s = 0; s < NGRP; s++){
        float4 v = src[s*stride4];
        a.x += v.x; a.y += v.y; a.z += v.z; a.w += v.w;
    }
    const float scale = 4.0f*PI_F*PI_F / (kn[0] * 25.0f);
    ((float4*)Q)[idx] = make_float4(scale*a.x, scale*a.y, scale*a.z, scale*a.w);
}

extern "C" void kernel_launch(void* const* d_in, const int* in_sizes, int n_in,
                              void* d_out, int out_size){
    const float* f      = (const float*)d_in[0];
    const float* kn     = (const float*)d_in[1];
    const float* phi    = (const float*)d_in[2];
    const float* psi    = (const float*)d_in[3];
    const float* phipsi = (const float*)d_in[4];
    float* Q = (float*)d_out;

    int nb = in_sizes[0] / N3;   // = 8
    if (nb > NB) nb = NB;

    k_fwd1   <<<nb*48,        NTHR>>>(f);
    k_fwd2   <<<nb*48,        NTHR>>>();
    k_mulfft <<<21*nb*48,     NTHR>>>(phi, psi, phipsi, nb);
    k_pair   <<<NGRP*nb*48,   NTHR>>>(nb);
    k_combine<<<(nb*N3/4+255)/256, 256>>>(Q, kn, nb);
}

// round 7
// speedup vs baseline: 1.3288x; 1.3020x over previous
#include <cuda_runtime.h>
#include <cstdint>

// ---------------------------------------------------------------------------
// Boltzmann collision operator, spectral method. N=48, B=8, M=5 -> 20 modes.
// Round 7 = Round 4 baseline (258.6us, best) + two surgical edits:
//   (1) k_mulfft: z-stage-A fused with the coalesced global load (shared tw,
//       NOT register twiddles -- those cost an occupancy cliff in R6).
//   (2) k_pair: plane padding 49->50 to turn 4-way stage-A bank conflicts
//       into the natural 2-way.
// ---------------------------------------------------------------------------

#define NN    48
#define N2P   (NN*NN)        // 2304
#define N3    (NN*NN*NN)     // 110592
#define NB    8
#define NJ    42             // 20 phi + 20 psi + phipsi + identity
#define NPG   3              // pairs per k_pair CTA
#define NGRP  7              // 21 / NPG partial slabs
#define LDP   49             // padded smem row, z-line phases (float2 units)
#define LDQ   50             // padded smem row, x-line phases (k_pair)
#define NTHR  384
#define PI_F  3.14159265358979323846f

// scratch (__device__ globals; no runtime allocation)
__device__ float2 g_spec[NB * N3];                    // ~7 MB
__device__ float2 g_S[(size_t)NB * NJ * N3];          // ~297 MB
__device__ float  g_part[(size_t)NGRP * NB * N3];     // ~25 MB signed partials

__device__ __forceinline__ float2 cadd(float2 a, float2 b){ return make_float2(a.x+b.x, a.y+b.y); }
__device__ __forceinline__ float2 csub(float2 a, float2 b){ return make_float2(a.x-b.x, a.y-b.y); }
__device__ __forceinline__ float2 cmul(float2 a, float2 b){
    return make_float2(a.x*b.x - a.y*b.y, a.x*b.y + a.y*b.x);
}

__device__ __forceinline__ void dft3(float2 a, float2 b, float2 c,
                                     float2& X0, float2& X1, float2& X2){
    float2 t1 = cadd(b, c);
    X0 = cadd(a, t1);
    float2 m = make_float2(a.x - 0.5f*t1.x, a.y - 0.5f*t1.y);
    const float K = 0.8660254037844386f;
    float2 s = make_float2(K*(b.x - c.x), K*(b.y - c.y));
    X1 = make_float2(m.x + s.y, m.y - s.x);   // m - i*s
    X2 = make_float2(m.x - s.y, m.y + s.x);   // m + i*s
}

// DFT6 + twiddle from shared tw row t = tw + n2*6
__device__ __forceinline__ void dft6_sh(const float2 x[6], const float2* t, float2 y[6]){
    float2 E0,E1,E2, O0,O1,O2;
    dft3(x[0], x[2], x[4], E0, E1, E2);
    dft3(x[1], x[3], x[5], O0, O1, O2);
    const float K = 0.8660254037844386f;
    float2 o1 = cmul(O1, make_float2( 0.5f, -K));
    float2 o2 = cmul(O2, make_float2(-0.5f, -K));
    y[0] = cadd(E0, O0);
    y[1] = cmul(cadd(E1, o1), t[1]);
    y[2] = cmul(cadd(E2, o2), t[2]);
    y[3] = cmul(csub(E0, O0), t[3]);
    y[4] = cmul(csub(E1, o1), t[4]);
    y[5] = cmul(csub(E2, o2), t[5]);
}

__device__ __forceinline__ void dft8(const float2* r, float2* o){
    float2 t0 = cadd(r[0],r[4]), t1 = csub(r[0],r[4]);
    float2 t2 = cadd(r[2],r[6]), t3 = csub(r[2],r[6]);
    float2 E0 = cadd(t0,t2), E2 = csub(t0,t2);
    float2 E1 = make_float2(t1.x + t3.y, t1.y - t3.x);
    float2 E3 = make_float2(t1.x - t3.y, t1.y + t3.x);
    float2 u0 = cadd(r[1],r[5]), u1 = csub(r[1],r[5]);
    float2 u2 = cadd(r[3],r[7]), u3 = csub(r[3],r[7]);
    float2 Q0 = cadd(u0,u2), Q2 = csub(u0,u2);
    float2 Q1 = make_float2(u1.x + u3.y, u1.y - u3.x);
    float2 Q3 = make_float2(u1.x - u3.y, u1.y + u3.x);
    const float S2 = 0.7071067811865476f;
    float2 p1 = cmul(Q1, make_float2( S2, -S2));
    float2 p2 = make_float2(Q2.y, -Q2.x);
    float2 p3 = cmul(Q3, make_float2(-S2, -S2));
    o[0] = cadd(E0,Q0); o[1] = cadd(E1,p1); o[2] = cadd(E2,p2); o[3] = cadd(E3,p3);
    o[4] = csub(E0,Q0); o[5] = csub(E1,p1); o[6] = csub(E2,p2); o[7] = csub(E3,p3);
}

// ---- stage A from smem, in place (thread-private slots), shared tw ----------
template <int LDR, int LDL>
__device__ __forceinline__ void stageA(float2* s, const float2* tw){
    const int w = threadIdx.x;
    int line = w >> 3, n2 = w & 7;
    float2* base = s + line*LDL + n2*LDR;
    float2 x[6], y[6];
    #pragma unroll
    for (int i = 0; i < 6; i++) x[i] = base[(8*i)*LDR];
    dft6_sh(x, tw + n2*6, y);
    #pragma unroll
    for (int k1 = 0; k1 < 6; k1++) base[(8*k1)*LDR] = y[k1];
}

// store stage-A outputs: slot (n2 + 8*k1) of the thread's line
template <int LDR, int LDL>
__device__ __forceinline__ void stA_store(float2* s, int line, int n2, const float2 y[6]){
    float2* base = s + line*LDL + n2*LDR;
    #pragma unroll
    for (int k1 = 0; k1 < 6; k1++) base[(8*k1)*LDR] = y[k1];
}

template <int LDR, int LDL>
__device__ __forceinline__ void stageB_load(const float2* s, int line, int k1, float2* r){
    const float2* base = s + line*LDL + (k1*8)*LDR;
    #pragma unroll
    for (int i = 0; i < 8; i++) r[i] = base[i*LDR];
}
template <int LDR, int LDL>
__device__ __forceinline__ void stageB_store(float2* s, int line, int k1, const float2* o){
    float2* out = s + line*LDL + k1*LDR;
    #pragma unroll
    for (int i = 0; i < 8; i++) out[(i*6)*LDR] = o[i];
}

// single-plane full FFT pass (in place)
template <int LDR, int LDL>
__device__ void fft_lines(float2* s, const float2* tw){
    stageA<LDR,LDL>(s, tw);
    __syncthreads();
    const int w = threadIdx.x;
    int line = w % 48, k1 = w / 48;
    bool act = (w < 288);
    float2 r[8];
    if (act) stageB_load<LDR,LDL>(s, line, k1, r);
    __syncthreads();
    if (act){
        float2 o[8];
        dft8(r, o);
        stageB_store<LDR,LDL>(s, line, k1, o);
    }
    __syncthreads();
}

// dual-plane stage B, in place, read-sync-write (shared barrier for both planes)
template <int LDR, int LDL>
__device__ __forceinline__ void stageB2_ip(float2* sA, float2* sB){
    const int w = threadIdx.x;
    int line = w % 48, k1 = w / 48;
    bool act = (w < 288);
    float2 ra[8], rb[8];
    if (act){
        stageB_load<LDR,LDL>(sA, line, k1, ra);
        stageB_load<LDR,LDL>(sB, line, k1, rb);
    }
    __syncthreads();
    if (act){
        float2 oa[8], ob[8];
        dft8(ra, oa);
        dft8(rb, ob);
        stageB_store<LDR,LDL>(sA, line, k1, oa);
        stageB_store<LDR,LDL>(sB, line, k1, ob);
    }
}

__device__ __forceinline__ void init_tw(float2* tw){
    if (threadIdx.x < 48){
        int n2 = threadIdx.x / 6, k1 = threadIdx.x % 6;
        float sv, cv;
        sincosf(-2.0f*PI_F * (float)(n2*k1) / 48.0f, &sv, &cv);
        tw[threadIdx.x] = make_float2(cv, sv);
    }
}

// K1: f * (-1)^(x+y+z), FFT along z then y; one x-plane per CTA.
__global__ void __launch_bounds__(NTHR) k_fwd1(const float* __restrict__ f){
    __shared__ float2 s[48*LDP];
    __shared__ float2 tw[48];
    init_tw(tw);
    int b = blockIdx.x / 48, x = blockIdx.x % 48;
    const float* src = f + (size_t)b*N3 + x*N2P;
    for (int i = threadIdx.x; i < N2P; i += NTHR){
        int y = i/48, z = i%48;
        float sg = ((x + y + z) & 1) ? -1.0f : 1.0f;
        s[y*LDP + z] = make_float2(sg * src[i], 0.0f);
    }
    __syncthreads();
    fft_lines<1,  LDP>(s, tw);   // z-lines
    fft_lines<LDP, 1 >(s, tw);   // y-lines
    float2* dst = g_spec + (size_t)b*N3 + x*N2P;
    for (int i = threadIdx.x; i < N2P; i += NTHR){
        int y = i/48, z = i%48;
        dst[i] = s[y*LDP + z];
    }
}

// K2: FFT along x, scale by 1/N^3, in place. One y-plane per CTA.
__global__ void __launch_bounds__(NTHR) k_fwd2(){
    __shared__ float2 s[48*LDP];
    __shared__ float2 tw[48];
    init_tw(tw);
    int b = blockIdx.x / 48, y = blockIdx.x % 48;
    float2* base = g_spec + (size_t)b*N3 + y*48;
    for (int i = threadIdx.x; i < N2P; i += NTHR){
        int x = i/48, z = i%48;
        s[x*LDP + z] = base[x*N2P + z];
    }
    __syncthreads();
    fft_lines<LDP, 1>(s, tw);    // x-lines
    const float inv = 1.0f / (float)N3;
    for (int i = threadIdx.x; i < N2P; i += NTHR){
        int x = i/48, z = i%48;
        float2 v = s[x*LDP + z];
        base[x*N2P + z] = make_float2(v.x*inv, v.y*inv);
    }
}

// K3: dual-plane uG = fs*wG, uH = fs*wH; FFT z then y -> g_S.
//     zA fused with the coalesced global load (shared tw); zB in place;
//     yA in place; yB stage-B registers -> global.
//     Batch fastest in blockIdx for weight L2 reuse.
__global__ void __launch_bounds__(NTHR) k_mulfft(const float* __restrict__ phi,
                                                 const float* __restrict__ psi,
                                                 const float* __restrict__ phipsi,
                                                 int nb){
    __shared__ float2 sG[48*LDP];
    __shared__ float2 sH[48*LDP];
    __shared__ float2 tw[48];
    init_tw(tw);
    int x  = blockIdx.x % 48;
    int bv = blockIdx.x / 48;
    int b  = bv % nb;
    int p  = bv / nb;            // 0..20
    int jG = (p < 20) ? p      : 40;
    int jH = (p < 20) ? 20 + p : 41;
    const int w = threadIdx.x;
    const float2* fs = g_spec + (size_t)b*N3 + x*N2P;
    const float* wG = (p < 20) ? (phi + (size_t)p*N3 + x*N2P) : (phipsi + (size_t)x*N2P);
    const float* wH = (p < 20) ? (psi + (size_t)p*N3 + x*N2P) : nullptr;

    // zA fused with global load: thread (yl, n2) reads z = n2+8i (coalesced).
    const int yl = w >> 3, n2 = w & 7;
    float2 xg[6], xh[6];
    {
        int off = yl*48 + n2;
        #pragma unroll
        for (int i = 0; i < 6; i++){
            float2 v = fs[off + 8*i];
            float gw = wG[off + 8*i];
            float hw = wH ? wH[off + 8*i] : 1.0f;
            xg[i] = make_float2(v.x*gw, v.y*gw);
            xh[i] = make_float2(v.x*hw, v.y*hw);
        }
    }
    __syncthreads();             // tw ready (loads overlapped with barrier)
    {
        float2 yg[6], yh[6];
        dft6_sh(xg, tw + n2*6, yg);
        dft6_sh(xh, tw + n2*6, yh);
        stA_store<1, LDP>(sG, yl, n2, yg);
        stA_store<1, LDP>(sH, yl, n2, yh);
    }
    __syncthreads();
    stageB2_ip<1, LDP>(sG, sH);  // zB in place (internal read-sync-write)
    __syncthreads();
    stageA<LDP, 1>(sG, tw);      // yA in place (thread-private slots)
    stageA<LDP, 1>(sH, tw);
    __syncthreads();
    // yB: smem -> registers -> global
    if (w < 288){
        int line = w % 48, k1 = w / 48;     // line = z
        float2 ra[8], rb[8], oa[8], ob[8];
        stageB_load<LDP,1>(sG, line, k1, ra);
        stageB_load<LDP,1>(sH, line, k1, rb);
        dft8(ra, oa);
        dft8(rb, ob);
        float2* dstG = g_S + (size_t)(b*NJ + jG)*N3 + x*N2P;
        float2* dstH = g_S + (size_t)(b*NJ + jH)*N3 + x*N2P;
        #pragma unroll
        for (int i = 0; i < 8; i++){
            dstG[(k1+6*i)*48 + line] = oa[i];
            dstH[(k1+6*i)*48 + line] = ob[i];
        }
    }
}

// K4: one (group g of NPG pairs, batch b, y-plane) per CTA.
//     Per pair: coalesced float4 staging, x-FFT stage A in smem (LDQ=50 pad
//     -> 2-way instead of 4-way conflicts), stage B in registers, signed
//     product accumulated across pairs, single store.
__global__ void __launch_bounds__(NTHR) k_pair(int nb){
    __shared__ float2 sG[48*LDQ];
    __shared__ float2 sH[48*LDQ];
    __shared__ float2 tw[48];
    init_tw(tw);
    int y  = blockIdx.x % 48;
    int bv = blockIdx.x / 48;
    int b  = bv % nb;
    int g  = bv / nb;            // 0..6
    const int w = threadIdx.x;
    const int line = w % 48, k1 = w / 48;
    const bool act = (w < 288);
    float acc[8];
    #pragma unroll
    for (int i = 0; i < 8; i++) acc[i] = 0.0f;

    for (int pp = 0; pp < NPG; pp++){
        int p  = g*NPG + pp;
        int jG = (p < 20) ? p      : 40;
        int jH = (p < 20) ? 20 + p : 41;
        float sgn = (p < 20) ? 1.0f : -1.0f;
        const float2* srcG = g_S + (size_t)(b*NJ + jG)*N3 + y*48;
        const float2* srcH = g_S + (size_t)(b*NJ + jH)*N3 + y*48;
        for (int i = threadIdx.x; i < N2P/2; i += NTHR){
            int x = i/24, q = i%24;
            int z0 = q*2;
            float4 gv = *(const float4*)(srcG + x*N2P + z0);
            float4 hv = *(const float4*)(srcH + x*N2P + z0);
            sG[x*LDQ + z0    ] = make_float2(gv.x, gv.y);
            sG[x*LDQ + z0 + 1] = make_float2(gv.z, gv.w);
            sH[x*LDQ + z0    ] = make_float2(hv.x, hv.y);
            sH[x*LDQ + z0 + 1] = make_float2(hv.z, hv.w);
        }
        __syncthreads();
        // x-lines: element stride LDQ, line (=z) stride 1
        stageA<LDQ, 1>(sG, tw);
        stageA<LDQ, 1>(sH, tw);
        __syncthreads();
        if (act){
            float2 ra[8], rb[8], oa[8], ob[8];
            stageB_load<LDQ,1>(sG, line, k1, ra);
            stageB_load<LDQ,1>(sH, line, k1, rb);
            dft8(ra, oa);
            dft8(rb, ob);
            #pragma unroll
            for (int i = 0; i < 8; i++)
                acc[i] += sgn * (oa[i].x*ob[i].x - oa[i].y*ob[i].y);
        }
        __syncthreads();   // protect sG/sH before next pair's loads
    }

    if (act){
        float* dst = g_part + (size_t)(g*nb + b)*N3 + y*48;
        #pragma unroll
        for (int i = 0; i < 8; i++){
            int x = k1 + 6*i;
            dst[(size_t)x*N2P + line] = acc[i];
        }
    }
}

// K5: deterministic combine: Q = scale * sum_g partial_g (float4).
__global__ void __launch_bounds__(256) k_combine(float* __restrict__ Q,
                                                 const float* __restrict__ kn,
                                                 int nb){
    int idx = blockIdx.x * 256 + threadIdx.x;
    int total4 = nb * N3 / 4;
    if (idx >= total4) return;
    const float4* src = (const float4*)g_part + idx;
    size_t stride4 = (size_t)nb * N3 / 4;
    float4 a = make_float4(0.f, 0.f, 0.f, 0.f);
    #pragma unroll
    for (int s = 0; s < NGRP; s++){
        float4 v = src[s*stride4];
        a.x += v.x; a.y += v.y; a.z += v.z; a.w += v.w;
    }
    const float scale = 4.0f*PI_F*PI_F / (kn[0] * 25.0f);
    ((float4*)Q)[idx] = make_float4(scale*a.x, scale*a.y, scale*a.z, scale*a.w);
}

extern "C" void kernel_launch(void* const* d_in, const int* in_sizes, int n_in,
                              void* d_out, int out_size){
    const float* f      = (const float*)d_in[0];
    const float* kn     = (const float*)d_in[1];
    const float* phi    = (const float*)d_in[2];
    const float* psi    = (const float*)d_in[3];
    const float* phipsi = (const float*)d_in[4];
    float* Q = (float*)d_out;

    int nb = in_sizes[0] / N3;   // = 8
    if (nb > NB) nb = NB;

    k_fwd1   <<<nb*48,        NTHR>>>(f);
    k_fwd2   <<<nb*48,        NTHR>>>();
    k_mulfft <<<21*nb*48,     NTHR>>>(phi, psi, phipsi, nb);
    k_pair   <<<NGRP*nb*48,   NTHR>>>(nb);
    k_combine<<<(nb*N3/4+255)/256, 256>>>(Q, kn, nb);
}

// round 8
// speedup vs baseline: 1.3379x; 1.0068x over previous
#include <cuda_runtime.h>
#include <cstdint>

// ---------------------------------------------------------------------------
// Boltzmann collision operator, spectral method. N=48, B=8, M=5 -> 20 modes.
// Round 8 = Round 7 (237.6us) + fork/join stream overlap: 3 chunks of 7 pairs,
//   k_mulfft(c) on the capture stream, k_pair(c) on a second stream gated by
//   an event -> pair(c) overlaps mulfft(c+1). k_pair now does 7 pairs/CTA
//   (one slab store per chunk, no RMW). float4 smem staging in k_pair.
// ---------------------------------------------------------------------------

#define NN    48
#define N2P   (NN*NN)        // 2304
#define N3    (NN*NN*NN)     // 110592
#define NB    8
#define NJ    42             // 20 phi + 20 psi + phipsi + identity
#define NCH   7              // pairs per chunk (= per k_pair CTA)
#define NCHUNK 3
#define LDP   49             // padded smem row, z/y-line phases (float2 units)
#define LDQ   50             // padded smem row, x-line phases (k_pair)
#define NTHR  384
#define PI_F  3.14159265358979323846f

// scratch (__device__ globals; no runtime allocation)
__device__ float2 g_spec[NB * N3];                        // ~7 MB
__device__ __align__(16) float2 g_S[(size_t)NB * NJ * N3];// ~297 MB
__device__ float  g_part[(size_t)NCHUNK * NB * N3];       // ~10.6 MB slabs

__device__ __forceinline__ float2 cadd(float2 a, float2 b){ return make_float2(a.x+b.x, a.y+b.y); }
__device__ __forceinline__ float2 csub(float2 a, float2 b){ return make_float2(a.x-b.x, a.y-b.y); }
__device__ __forceinline__ float2 cmul(float2 a, float2 b){
    return make_float2(a.x*b.x - a.y*b.y, a.x*b.y + a.y*b.x);
}

__device__ __forceinline__ void dft3(float2 a, float2 b, float2 c,
                                     float2& X0, float2& X1, float2& X2){
    float2 t1 = cadd(b, c);
    X0 = cadd(a, t1);
    float2 m = make_float2(a.x - 0.5f*t1.x, a.y - 0.5f*t1.y);
    const float K = 0.8660254037844386f;
    float2 s = make_float2(K*(b.x - c.x), K*(b.y - c.y));
    X1 = make_float2(m.x + s.y, m.y - s.x);   // m - i*s
    X2 = make_float2(m.x - s.y, m.y + s.x);   // m + i*s
}

// DFT6 + twiddle from shared tw row t = tw + n2*6
__device__ __forceinline__ void dft6_sh(const float2 x[6], const float2* t, float2 y[6]){
    float2 E0,E1,E2, O0,O1,O2;
    dft3(x[0], x[2], x[4], E0, E1, E2);
    dft3(x[1], x[3], x[5], O0, O1, O2);
    const float K = 0.8660254037844386f;
    float2 o1 = cmul(O1, make_float2( 0.5f, -K));
    float2 o2 = cmul(O2, make_float2(-0.5f, -K));
    y[0] = cadd(E0, O0);
    y[1] = cmul(cadd(E1, o1), t[1]);
    y[2] = cmul(cadd(E2, o2), t[2]);
    y[3] = cmul(csub(E0, O0), t[3]);
    y[4] = cmul(csub(E1, o1), t[4]);
    y[5] = cmul(csub(E2, o2), t[5]);
}

__device__ __forceinline__ void dft8(const float2* r, float2* o){
    float2 t0 = cadd(r[0],r[4]), t1 = csub(r[0],r[4]);
    float2 t2 = cadd(r[2],r[6]), t3 = csub(r[2],r[6]);
    float2 E0 = cadd(t0,t2), E2 = csub(t0,t2);
    float2 E1 = make_float2(t1.x + t3.y, t1.y - t3.x);
    float2 E3 = make_float2(t1.x - t3.y, t1.y + t3.x);
    float2 u0 = cadd(r[1],r[5]), u1 = csub(r[1],r[5]);
    float2 u2 = cadd(r[3],r[7]), u3 = csub(r[3],r[7]);
    float2 Q0 = cadd(u0,u2), Q2 = csub(u0,u2);
    float2 Q1 = make_float2(u1.x + u3.y, u1.y - u3.x);
    float2 Q3 = make_float2(u1.x - u3.y, u1.y + u3.x);
    const float S2 = 0.7071067811865476f;
    float2 p1 = cmul(Q1, make_float2( S2, -S2));
    float2 p2 = make_float2(Q2.y, -Q2.x);
    float2 p3 = cmul(Q3, make_float2(-S2, -S2));
    o[0] = cadd(E0,Q0); o[1] = cadd(E1,p1); o[2] = cadd(E2,p2); o[3] = cadd(E3,p3);
    o[4] = csub(E0,Q0); o[5] = csub(E1,p1); o[6] = csub(E2,p2); o[7] = csub(E3,p3);
}

// ---- stage A from smem, in place (thread-private slots), shared tw ----------
template <int LDR, int LDL>
__device__ __forceinline__ void stageA(float2* s, const float2* tw){
    const int w = threadIdx.x;
    int line = w >> 3, n2 = w & 7;
    float2* base = s + line*LDL + n2*LDR;
    float2 x[6], y[6];
    #pragma unroll
    for (int i = 0; i < 6; i++) x[i] = base[(8*i)*LDR];
    dft6_sh(x, tw + n2*6, y);
    #pragma unroll
    for (int k1 = 0; k1 < 6; k1++) base[(8*k1)*LDR] = y[k1];
}

// store stage-A outputs: slot (n2 + 8*k1) of the thread's line
template <int LDR, int LDL>
__device__ __forceinline__ void stA_store(float2* s, int line, int n2, const float2 y[6]){
    float2* base = s + line*LDL + n2*LDR;
    #pragma unroll
    for (int k1 = 0; k1 < 6; k1++) base[(8*k1)*LDR] = y[k1];
}

template <int LDR, int LDL>
__device__ __forceinline__ void stageB_load(const float2* s, int line, int k1, float2* r){
    const float2* base = s + line*LDL + (k1*8)*LDR;
    #pragma unroll
    for (int i = 0; i < 8; i++) r[i] = base[i*LDR];
}
template <int LDR, int LDL>
__device__ __forceinline__ void stageB_store(float2* s, int line, int k1, const float2* o){
    float2* out = s + line*LDL + k1*LDR;
    #pragma unroll
    for (int i = 0; i < 8; i++) out[(i*6)*LDR] = o[i];
}

// single-plane full FFT pass (in place)
template <int LDR, int LDL>
__device__ void fft_lines(float2* s, const float2* tw){
    stageA<LDR,LDL>(s, tw);
    __syncthreads();
    const int w = threadIdx.x;
    int line = w % 48, k1 = w / 48;
    bool act = (w < 288);
    float2 r[8];
    if (act) stageB_load<LDR,LDL>(s, line, k1, r);
    __syncthreads();
    if (act){
        float2 o[8];
        dft8(r, o);
        stageB_store<LDR,LDL>(s, line, k1, o);
    }
    __syncthreads();
}

// dual-plane stage B, in place, read-sync-write (shared barrier for both planes)
template <int LDR, int LDL>
__device__ __forceinline__ void stageB2_ip(float2* sA, float2* sB){
    const int w = threadIdx.x;
    int line = w % 48, k1 = w / 48;
    bool act = (w < 288);
    float2 ra[8], rb[8];
    if (act){
        stageB_load<LDR,LDL>(sA, line, k1, ra);
        stageB_load<LDR,LDL>(sB, line, k1, rb);
    }
    __syncthreads();
    if (act){
        float2 oa[8], ob[8];
        dft8(ra, oa);
        dft8(rb, ob);
        stageB_store<LDR,LDL>(sA, line, k1, oa);
        stageB_store<LDR,LDL>(sB, line, k1, ob);
    }
}

__device__ __forceinline__ void init_tw(float2* tw){
    if (threadIdx.x < 48){
        int n2 = threadIdx.x / 6, k1 = threadIdx.x % 6;
        float sv, cv;
        sincosf(-2.0f*PI_F * (float)(n2*k1) / 48.0f, &sv, &cv);
        tw[threadIdx.x] = make_float2(cv, sv);
    }
}

// K1: f * (-1)^(x+y+z), FFT along z then y; one x-plane per CTA.
__global__ void __launch_bounds__(NTHR) k_fwd1(const float* __restrict__ f){
    __shared__ float2 s[48*LDP];
    __shared__ float2 tw[48];
    init_tw(tw);
    int b = blockIdx.x / 48, x = blockIdx.x % 48;
    const float* src = f + (size_t)b*N3 + x*N2P;
    for (int i = threadIdx.x; i < N2P; i += NTHR){
        int y = i/48, z = i%48;
        float sg = ((x + y + z) & 1) ? -1.0f : 1.0f;
        s[y*LDP + z] = make_float2(sg * src[i], 0.0f);
    }
    __syncthreads();
    fft_lines<1,  LDP>(s, tw);   // z-lines
    fft_lines<LDP, 1 >(s, tw);   // y-lines
    float2* dst = g_spec + (size_t)b*N3 + x*N2P;
    for (int i = threadIdx.x; i < N2P; i += NTHR){
        int y = i/48, z = i%48;
        dst[i] = s[y*LDP + z];
    }
}

// K2: FFT along x, scale by 1/N^3, in place. One y-plane per CTA.
__global__ void __launch_bounds__(NTHR) k_fwd2(){
    __shared__ float2 s[48*LDP];
    __shared__ float2 tw[48];
    init_tw(tw);
    int b = blockIdx.x / 48, y = blockIdx.x % 48;
    float2* base = g_spec + (size_t)b*N3 + y*48;
    for (int i = threadIdx.x; i < N2P; i += NTHR){
        int x = i/48, z = i%48;
        s[x*LDP + z] = base[x*N2P + z];
    }
    __syncthreads();
    fft_lines<LDP, 1>(s, tw);    // x-lines
    const float inv = 1.0f / (float)N3;
    for (int i = threadIdx.x; i < N2P; i += NTHR){
        int x = i/48, z = i%48;
        float2 v = s[x*LDP + z];
        base[x*N2P + z] = make_float2(v.x*inv, v.y*inv);
    }
}

// K3 (per chunk): dual-plane uG = fs*wG, uH = fs*wH; FFT z then y -> g_S.
//     zA fused with the coalesced global load; zB in place; yA in place;
//     yB stage-B registers -> global. Batch fastest for weight L2 reuse.
__global__ void __launch_bounds__(NTHR) k_mulfft(const float* __restrict__ phi,
                                                 const float* __restrict__ psi,
                                                 const float* __restrict__ phipsi,
                                                 int nb, int p0){
    __shared__ float2 sG[48*LDP];
    __shared__ float2 sH[48*LDP];
    __shared__ float2 tw[48];
    init_tw(tw);
    int x  = blockIdx.x % 48;
    int bv = blockIdx.x / 48;
    int b  = bv % nb;
    int p  = p0 + bv / nb;       // 0..20
    int jG = (p < 20) ? p      : 40;
    int jH = (p < 20) ? 20 + p : 41;
    const int w = threadIdx.x;
    const float2* fs = g_spec + (size_t)b*N3 + x*N2P;
    const float* wG = (p < 20) ? (phi + (size_t)p*N3 + x*N2P) : (phipsi + (size_t)x*N2P);
    const float* wH = (p < 20) ? (psi + (size_t)p*N3 + x*N2P) : nullptr;

    // zA fused with global load: thread (yl, n2) reads z = n2+8i (coalesced).
    const int yl = w >> 3, n2 = w & 7;
    float2 xg[6], xh[6];
    {
        int off = yl*48 + n2;
        #pragma unroll
        for (int i = 0; i < 6; i++){
            float2 v = fs[off + 8*i];
            float gw = wG[off + 8*i];
            float hw = wH ? wH[off + 8*i] : 1.0f;
            xg[i] = make_float2(v.x*gw, v.y*gw);
            xh[i] = make_float2(v.x*hw, v.y*hw);
        }
    }
    __syncthreads();             // tw ready (loads overlapped with barrier)
    {
        float2 yg[6], yh[6];
        dft6_sh(xg, tw + n2*6, yg);
        dft6_sh(xh, tw + n2*6, yh);
        stA_store<1, LDP>(sG, yl, n2, yg);
        stA_store<1, LDP>(sH, yl, n2, yh);
    }
    __syncthreads();
    stageB2_ip<1, LDP>(sG, sH);  // zB in place (internal read-sync-write)
    __syncthreads();
    stageA<LDP, 1>(sG, tw);      // yA in place (thread-private slots)
    stageA<LDP, 1>(sH, tw);
    __syncthreads();
    // yB: smem -> registers -> global
    if (w < 288){
        int line = w % 48, k1 = w / 48;     // line = z
        float2 ra[8], rb[8], oa[8], ob[8];
        stageB_load<LDP,1>(sG, line, k1, ra);
        stageB_load<LDP,1>(sH, line, k1, rb);
        dft8(ra, oa);
        dft8(rb, ob);
        float2* dstG = g_S + (size_t)(b*NJ + jG)*N3 + x*N2P;
        float2* dstH = g_S + (size_t)(b*NJ + jH)*N3 + x*N2P;
        #pragma unroll
        for (int i = 0; i < 8; i++){
            dstG[(k1+6*i)*48 + line] = oa[i];
            dstH[(k1+6*i)*48 + line] = ob[i];
        }
    }
}

// K4 (per chunk): one (batch b, y-plane) per CTA covering all 7 chunk pairs.
//     Per pair: float4-coalesced staging, x-FFT stage A in smem (LDQ=50 ->
//     conflict-free), stage B in registers, signed product accumulated,
//     single slab store (each slab written exactly once -- no RMW).
__global__ void __launch_bounds__(NTHR) k_pair(int nb, int p0, int slab){
    __shared__ __align__(16) float2 sG[48*LDQ];
    __shared__ __align__(16) float2 sH[48*LDQ];
    __shared__ float2 tw[48];
    init_tw(tw);
    int y = blockIdx.x % 48;
    int b = blockIdx.x / 48;
    const int w = threadIdx.x;
    const int line = w % 48, k1 = w / 48;
    const bool act = (w < 288);
    float acc[8];
    #pragma unroll
    for (int i = 0; i < 8; i++) acc[i] = 0.0f;

    for (int pp = 0; pp < NCH; pp++){
        int p  = p0 + pp;
        int jG = (p < 20) ? p      : 40;
        int jH = (p < 20) ? 20 + p : 41;
        float sgn = (p < 20) ? 1.0f : -1.0f;
        const float2* srcG = g_S + (size_t)(b*NJ + jG)*N3 + y*48;
        const float2* srcH = g_S + (size_t)(b*NJ + jH)*N3 + y*48;
        for (int i = threadIdx.x; i < N2P/2; i += NTHR){
            int x = i/24, q = i%24;
            int z0 = q*2;
            float4 gv = *(const float4*)(srcG + x*N2P + z0);
            float4 hv = *(const float4*)(srcH + x*N2P + z0);
            *(float4*)(sG + x*LDQ + z0) = gv;
            *(float4*)(sH + x*LDQ + z0) = hv;
        }
        __syncthreads();
        // x-lines: element stride LDQ, line (=z) stride 1
        stageA<LDQ, 1>(sG, tw);
        stageA<LDQ, 1>(sH, tw);
        __syncthreads();
        if (act){
            float2 ra[8], rb[8], oa[8], ob[8];
            stageB_load<LDQ,1>(sG, line, k1, ra);
            stageB_load<LDQ,1>(sH, line, k1, rb);
            dft8(ra, oa);
            dft8(rb, ob);
            #pragma unroll
            for (int i = 0; i < 8; i++)
                acc[i] += sgn * (oa[i].x*ob[i].x - oa[i].y*ob[i].y);
        }
        __syncthreads();   // protect sG/sH before next pair's loads
    }

    if (act){
        float* dst = g_part + (size_t)(slab*nb + b)*N3 + y*48;
        #pragma unroll
        for (int i = 0; i < 8; i++){
            int x = k1 + 6*i;
            dst[(size_t)x*N2P + line] = acc[i];
        }
    }
}

// K5: deterministic combine: Q = scale * sum_c slab_c (float4).
__global__ void __launch_bounds__(256) k_combine(float* __restrict__ Q,
                                                 const float* __restrict__ kn,
                                                 int nb){
    int idx = blockIdx.x * 256 + threadIdx.x;
    int total4 = nb * N3 / 4;
    if (idx >= total4) return;
    const float4* src = (const float4*)g_part + idx;
    size_t stride4 = (size_t)nb * N3 / 4;
    float4 a = src[0];
    float4 c = src[stride4];
    float4 d = src[2*stride4];
    const float scale = 4.0f*PI_F*PI_F / (kn[0] * 25.0f);
    ((float4*)Q)[idx] = make_float4(scale*(a.x+c.x+d.x), scale*(a.y+c.y+d.y),
                                    scale*(a.z+c.z+d.z), scale*(a.w+c.w+d.w));
}

extern "C" void kernel_launch(void* const* d_in, const int* in_sizes, int n_in,
                              void* d_out, int out_size){
    const float* f      = (const float*)d_in[0];
    const float* kn     = (const float*)d_in[1];
    const float* phi    = (const float*)d_in[2];
    const float* psi    = (const float*)d_in[3];
    const float* phipsi = (const float*)d_in[4];
    float* Q = (float*)d_out;

    int nb = in_sizes[0] / N3;   // = 8
    if (nb > NB) nb = NB;

    // Fork/join overlap: mulfft chunks on the main (capture) stream, pair
    // chunks on a second stream gated by events. pair(c) overlaps mulfft(c+1).
    cudaStream_t s2;
    cudaStreamCreateWithFlags(&s2, cudaStreamNonBlocking);
    cudaEvent_t evM[NCHUNK], evJ;
    for (int c = 0; c < NCHUNK; c++)
        cudaEventCreateWithFlags(&evM[c], cudaEventDisableTiming);
    cudaEventCreateWithFlags(&evJ, cudaEventDisableTiming);

    k_fwd1<<<nb*48, NTHR>>>(f);
    k_fwd2<<<nb*48, NTHR>>>();
    for (int c = 0; c < NCHUNK; c++){
        k_mulfft<<<NCH*nb*48, NTHR>>>(phi, psi, phipsi, nb, NCH*c);
        cudaEventRecord(evM[c], 0);
        cudaStreamWaitEvent(s2, evM[c], 0);
        k_pair<<<nb*48, NTHR, 0, s2>>>(nb, NCH*c, c);
    }
    cudaEventRecord(evJ, s2);
    cudaStreamWaitEvent(0, evJ, 0);
    k_combine<<<(nb*N3/4 + 255)/256, 256>>>(Q, kn, nb);
}